// round 10
// baseline (speedup 1.0000x reference)
#include <cuda_runtime.h>
#include <cuda_bf16.h>

// MorletTransform via per-harmonic Goertzel recurrence (f32x2 packed lanes).
// R10: MUFU-pipe evacuation.
//  - Gaussian window precomputed once per launch into __device__ g_win
//    (init kernel), main kernel does audio*g_win only (no __expf).
//  - Segment rotation e^{-i*th*(64s+63)} = E63 * E64^s applied in the tail
//    warp as a running complex multiply (FMA only); workers store UNROTATED
//    Goertzel results (no per-thread __sincosf).
// Loop (unchanged): quad = tid&15 -> harmonics 4q+1..4q+4 as two f32x2
// chains; seg = tid>>4 -> 64-sample segment; 1 LDS.128 + 8 FFMA2 / 2 samples.

#define TWO_PI_F 6.28318530717958647692f

__device__ float g_win[1024];   // normalizer * gauss[n]

__device__ __forceinline__ unsigned long long fma2(unsigned long long a,
                                                   unsigned long long b,
                                                   unsigned long long c) {
    unsigned long long d;
    asm("fma.rn.f32x2 %0, %1, %2, %3;" : "=l"(d) : "l"(a), "l"(b), "l"(c));
    return d;
}
__device__ __forceinline__ unsigned long long pk(float lo, float hi) {
    unsigned long long d;
    asm("mov.b64 %0, {%1, %2};" : "=l"(d) : "f"(lo), "f"(hi));
    return d;
}
__device__ __forceinline__ void upk(unsigned long long v, float& lo, float& hi) {
    asm("mov.b64 {%0, %1}, %2;" : "=f"(lo), "=f"(hi) : "l"(v));
}

__global__ void win_init_kernel() {
    // normalizer = 1/sqrt(pi*tp), tp = sr/half_bw = 16000
    const float normalizer = rsqrtf(3.14159265358979f * 16000.0f);
    const float inv_tp     = 1.0f / 16000.0f;
    int n = threadIdx.x * 4;
    float4 o;
    float d0 = (float)(n + 0 - 512), d1 = (float)(n + 1 - 512);
    float d2 = (float)(n + 2 - 512), d3 = (float)(n + 3 - 512);
    o.x = normalizer * __expf(-d0 * d0 * inv_tp);
    o.y = normalizer * __expf(-d1 * d1 * inv_tp);
    o.z = normalizer * __expf(-d2 * d2 * inv_tp);
    o.w = normalizer * __expf(-d3 * d3 * inv_tp);
    ((float4*)g_win)[threadIdx.x] = o;
}

__global__ void __launch_bounds__(256)
morlet_kernel(const float* __restrict__ audio,
              const float* __restrict__ f0,
              float* __restrict__ out_hd,
              float* __restrict__ out_amp) {
    const int f   = blockIdx.x;
    const int tid = threadIdx.x;

    __shared__ __align__(16) unsigned long long w2[1024];   // (w[n],w[n]); 8KB
    __shared__ __align__(16) float2 sPart[16 * 64];         // [seg][harmonic] y; 8KB
    __shared__ __align__(8)  float sCth[64];
    __shared__ __align__(8)  float sSth[64];
    __shared__ __align__(16) float2 sE63[64];               // e^{-i*2pi*frac(63 fc)}
    __shared__ __align__(16) float2 sE64[64];               // e^{-i*2pi*frac(64 fc)}

    const float inv_sr = 1.0f / 16000.0f;

    // --- issue GMEM loads up front (independent, in flight together) ---
    float4 a = ((const float4*)audio)[(size_t)f * 256 + tid];
    float4 g = __ldg(&((const float4*)g_win)[tid]);
    const float f0v = f0[f];

    // --- per-harmonic coefficients (overlaps the loads above).
    //     Recurrence coeff: accurate sincosf (cos error amplified by
    //     1/sin(theta) ~51 at k=1). Rotation phasors E63/E64: absolute
    //     phases, __sincosf precision is sufficient. ---
    if (tid < 64) {
        float fc = f0v * (float)(tid + 1) * inv_sr;
        float s, c;
        sincosf(TWO_PI_F * fc, &s, &c);
        sCth[tid] = c;
        sSth[tid] = s;
        float p63 = fc * 63.0f; p63 -= floorf(p63);
        float p64 = fc * 64.0f; p64 -= floorf(p64);
        float s63, c63, s64, c64;
        __sincosf(TWO_PI_F * p63, &s63, &c63);
        __sincosf(TWO_PI_F * p64, &s64, &c64);
        sE63[tid] = make_float2(c63, -s63);
        sE64[tid] = make_float2(c64, -s64);
    }

    // --- windowed frame: w[n] = audio[n] * g_win[n], stored duplicated ---
    {
        unsigned long long o0 = pk(a.x * g.x, a.x * g.x);
        unsigned long long o1 = pk(a.y * g.y, a.y * g.y);
        unsigned long long o2 = pk(a.z * g.z, a.z * g.z);
        unsigned long long o3 = pk(a.w * g.w, a.w * g.w);
        ((ulonglong2*)w2)[tid * 2]     = make_ulonglong2(o0, o1);
        ((ulonglong2*)w2)[tid * 2 + 1] = make_ulonglong2(o2, o3);
    }
    __syncthreads();   // barrier #1: w2 + coefficients ready

    const int quad = tid & 15;   // harmonics 4q+1 .. 4q+4
    const int seg  = tid >> 4;   // 16 segments of 64 samples

    float2 cthP = ((const float2*)sCth)[2 * quad];       // harmonics 4q+1, 4q+2
    float2 sthP = ((const float2*)sSth)[2 * quad];
    float2 cthQ = ((const float2*)sCth)[2 * quad + 1];   // harmonics 4q+3, 4q+4
    float2 sthQ = ((const float2*)sSth)[2 * quad + 1];
    const unsigned long long C2P  = pk(2.0f * cthP.x, 2.0f * cthP.y);
    const unsigned long long C2Q  = pk(2.0f * cthQ.x, 2.0f * cthQ.y);
    const unsigned long long NEG1 = pk(-1.0f, -1.0f);

    // --- Goertzel: two f32x2 chains over this thread's 64-sample segment ---
    const ulonglong2* wq = (const ulonglong2*)(w2 + seg * 64);

    unsigned long long p1 = 0ull, p2 = 0ull;  // chain P (harmonics 4q+1,4q+2)
    unsigned long long q1 = 0ull, q2 = 0ull;  // chain Q (harmonics 4q+3,4q+4)
    #pragma unroll
    for (int m = 0; m < 32; ++m) {
        ulonglong2 wv = wq[m];                         // 2 samples, duplicated
        unsigned long long t0 = fma2(NEG1, p2, wv.x);  // w - s_{n-2}
        unsigned long long s0 = fma2(C2P, p1, t0);
        unsigned long long u0 = fma2(NEG1, q2, wv.x);
        unsigned long long v0 = fma2(C2Q, q1, u0);
        unsigned long long t1 = fma2(NEG1, p1, wv.y);
        unsigned long long sn = fma2(C2P, s0, t1);
        unsigned long long u1 = fma2(NEG1, q1, wv.y);
        unsigned long long vn = fma2(C2Q, v0, u1);
        p2 = s0; p1 = sn;
        q2 = v0; q1 = vn;
    }

    // --- store UNROTATED y = (s1 - cos*s2, sin*s2) per harmonic (no trig) ---
    {
        float x1A, x1B, x2A, x2B;
        upk(p1, x1A, x1B); upk(p2, x2A, x2B);
        sPart[seg * 64 + 4 * quad + 0] =
            make_float2(fmaf(-cthP.x, x2A, x1A), sthP.x * x2A);
        sPart[seg * 64 + 4 * quad + 1] =
            make_float2(fmaf(-cthP.y, x2B, x1B), sthP.y * x2B);
        upk(q1, x1A, x1B); upk(q2, x2A, x2B);
        sPart[seg * 64 + 4 * quad + 2] =
            make_float2(fmaf(-cthQ.x, x2A, x1A), sthQ.x * x2A);
        sPart[seg * 64 + 4 * quad + 3] =
            make_float2(fmaf(-cthQ.y, x2B, x1B), sthQ.y * x2B);
    }
    __syncthreads();   // barrier #2: partials visible

    // --- single-warp finish: lane l owns harmonics h=2l, 2l+1.
    //     Rotation for segment s: rot = E63 * E64^s, applied as a running
    //     complex product (FMA only). ---
    if (tid < 32) {
        float4 e63 = *(const float4*)&sE63[2 * tid];  // (h0.re,h0.im,h1.re,h1.im)
        float4 e64 = *(const float4*)&sE64[2 * tid];
        float r0re = e63.x, r0im = e63.y;
        float r1re = e63.z, r1im = e63.w;
        float ar0 = 0.0f, ai0 = 0.0f, ar1 = 0.0f, ai1 = 0.0f;

        #pragma unroll
        for (int s = 0; s < 16; ++s) {
            float4 pq = *(const float4*)&sPart[s * 64 + 2 * tid];
            // acc += y * rot   (rot = e^{-i phi})
            ar0 = fmaf(pq.x, r0re, ar0); ar0 = fmaf(-pq.y, r0im, ar0);
            ai0 = fmaf(pq.x, r0im, ai0); ai0 = fmaf( pq.y, r0re, ai0);
            ar1 = fmaf(pq.z, r1re, ar1); ar1 = fmaf(-pq.w, r1im, ar1);
            ai1 = fmaf(pq.z, r1im, ai1); ai1 = fmaf( pq.w, r1re, ai1);
            // rot *= E64
            float n0re = fmaf(r0re, e64.x, -r0im * e64.y);
            float n0im = fmaf(r0re, e64.y,  r0im * e64.x);
            float n1re = fmaf(r1re, e64.z, -r1im * e64.w);
            float n1im = fmaf(r1re, e64.w,  r1im * e64.z);
            r0re = n0re; r0im = n0im;
            r1re = n1re; r1im = n1im;
        }

        float mag0 = sqrtf(ar0 * ar0 + ai0 * ai0);
        float mag1 = sqrtf(ar1 * ar1 + ai1 * ai1);
        float fch0 = f0v * (float)(2 * tid + 1) * inv_sr;
        float fch1 = f0v * (float)(2 * tid + 2) * inv_sr;
        if (fch0 > 0.5f) mag0 = 0.0f;   // Nyquist mask
        if (fch1 > 0.5f) mag1 = 0.0f;

        float s = mag0 + mag1;
        #pragma unroll
        for (int o = 16; o > 0; o >>= 1)
            s += __shfl_xor_sync(0xffffffffu, s, o);   // amp in all lanes

        float inv = 1.0f / s;
        ((float2*)out_hd)[f * 32 + tid] = make_float2(mag0 * inv, mag1 * inv);
        if (tid == 0)
            out_amp[f] = fminf(fmaxf(s * 2.0f, 0.0f), 1.0f);
    }
}

extern "C" void kernel_launch(void* const* d_in, const int* in_sizes, int n_in,
                              void* d_out, int out_size) {
    const float* audio = (const float*)d_in[0];
    const float* f0    = (const float*)d_in[1];
    const int frames   = in_sizes[1];  // 2*250*1 = 500
    float* out         = (float*)d_out;
    win_init_kernel<<<1, 256>>>();     // writes the same values every launch
    morlet_kernel<<<frames, 256>>>(audio, f0, out, out + (size_t)frames * 64);
}

// round 11
// speedup vs baseline: 1.2063x; 1.2063x over previous
#include <cuda_runtime.h>
#include <cuda_bf16.h>

// MorletTransform via per-harmonic Goertzel recurrence (f32x2 packed lanes).
// Single launch. R10 structure with the window computed inline (no init
// kernel): w[n] = audio[n] * normalizer * exp(-(n-512)^2/tp).
// Mapping: 256 threads/frame; quad = tid&15 -> harmonics 4q+1..4q+4 as two
// f32x2 Goertzel chains; seg = tid>>4 -> 64-sample segment.
// Workers store UNROTATED y; single-warp tail applies rotation
// E63 * E64^s via two independent even/odd phasor chains (E128 = E64^2).

#define TWO_PI_F 6.28318530717958647692f

__device__ __forceinline__ unsigned long long fma2(unsigned long long a,
                                                   unsigned long long b,
                                                   unsigned long long c) {
    unsigned long long d;
    asm("fma.rn.f32x2 %0, %1, %2, %3;" : "=l"(d) : "l"(a), "l"(b), "l"(c));
    return d;
}
__device__ __forceinline__ unsigned long long pk(float lo, float hi) {
    unsigned long long d;
    asm("mov.b64 %0, {%1, %2};" : "=l"(d) : "f"(lo), "f"(hi));
    return d;
}
__device__ __forceinline__ void upk(unsigned long long v, float& lo, float& hi) {
    asm("mov.b64 {%0, %1}, %2;" : "=f"(lo), "=f"(hi) : "l"(v));
}

__global__ void __launch_bounds__(256)
morlet_kernel(const float* __restrict__ audio,
              const float* __restrict__ f0,
              float* __restrict__ out_hd,
              float* __restrict__ out_amp) {
    const int f   = blockIdx.x;
    const int tid = threadIdx.x;

    __shared__ __align__(16) unsigned long long w2[1024];   // (w[n],w[n]); 8KB
    __shared__ __align__(16) float2 sPart[16 * 64];         // [seg][harmonic] y; 8KB
    __shared__ __align__(8)  float sCth[64];
    __shared__ __align__(8)  float sSth[64];
    __shared__ __align__(16) float2 sE63[64];               // e^{-i*2pi*frac(63 fc)}
    __shared__ __align__(16) float2 sE64[64];               // e^{-i*2pi*frac(64 fc)}

    // normalizer = 1/sqrt(pi*tp), tp = sr/half_bw = 16000
    const float normalizer = rsqrtf(3.14159265358979f * 16000.0f);
    const float inv_tp     = 1.0f / 16000.0f;
    const float inv_sr     = 1.0f / 16000.0f;

    // --- issue GMEM loads up front (independent, in flight together) ---
    float4 a = ((const float4*)audio)[(size_t)f * 256 + tid];
    const float f0v = f0[f];

    // --- per-harmonic coefficients (overlaps the audio load).
    //     Recurrence coeff: accurate sincosf (cos error amplified by
    //     1/sin(theta) ~51 at k=1). Rotation phasors E63/E64: absolute
    //     phases, __sincosf precision is sufficient. ---
    if (tid < 64) {
        float fc = f0v * (float)(tid + 1) * inv_sr;
        float s, c;
        sincosf(TWO_PI_F * fc, &s, &c);
        sCth[tid] = c;
        sSth[tid] = s;
        float p63 = fc * 63.0f; p63 -= floorf(p63);
        float p64 = fc * 64.0f; p64 -= floorf(p64);
        float s63, c63, s64, c64;
        __sincosf(TWO_PI_F * p63, &s63, &c63);
        __sincosf(TWO_PI_F * p64, &s64, &c64);
        sE63[tid] = make_float2(c63, -s63);
        sE64[tid] = make_float2(c64, -s64);
    }

    // --- windowed frame: w[n] = audio[n]*normalizer*gauss[n], duplicated ---
    {
        int n = tid * 4;
        float v[4] = {a.x, a.y, a.z, a.w};
        unsigned long long o[4];
        #pragma unroll
        for (int i = 0; i < 4; ++i) {
            float d  = (float)(n + i - 512);
            float wv = v[i] * (normalizer * __expf(-d * d * inv_tp));
            o[i] = pk(wv, wv);
        }
        ((ulonglong2*)w2)[tid * 2]     = make_ulonglong2(o[0], o[1]);
        ((ulonglong2*)w2)[tid * 2 + 1] = make_ulonglong2(o[2], o[3]);
    }
    __syncthreads();   // barrier #1: w2 + coefficients ready

    const int quad = tid & 15;   // harmonics 4q+1 .. 4q+4
    const int seg  = tid >> 4;   // 16 segments of 64 samples

    float2 cthP = ((const float2*)sCth)[2 * quad];       // harmonics 4q+1, 4q+2
    float2 sthP = ((const float2*)sSth)[2 * quad];
    float2 cthQ = ((const float2*)sCth)[2 * quad + 1];   // harmonics 4q+3, 4q+4
    float2 sthQ = ((const float2*)sSth)[2 * quad + 1];
    const unsigned long long C2P  = pk(2.0f * cthP.x, 2.0f * cthP.y);
    const unsigned long long C2Q  = pk(2.0f * cthQ.x, 2.0f * cthQ.y);
    const unsigned long long NEG1 = pk(-1.0f, -1.0f);

    // --- Goertzel: two f32x2 chains over this thread's 64-sample segment ---
    const ulonglong2* wq = (const ulonglong2*)(w2 + seg * 64);

    unsigned long long p1 = 0ull, p2 = 0ull;  // chain P (harmonics 4q+1,4q+2)
    unsigned long long q1 = 0ull, q2 = 0ull;  // chain Q (harmonics 4q+3,4q+4)
    #pragma unroll
    for (int m = 0; m < 32; ++m) {
        ulonglong2 wv = wq[m];                         // 2 samples, duplicated
        unsigned long long t0 = fma2(NEG1, p2, wv.x);  // w - s_{n-2}
        unsigned long long s0 = fma2(C2P, p1, t0);
        unsigned long long u0 = fma2(NEG1, q2, wv.x);
        unsigned long long v0 = fma2(C2Q, q1, u0);
        unsigned long long t1 = fma2(NEG1, p1, wv.y);
        unsigned long long sn = fma2(C2P, s0, t1);
        unsigned long long u1 = fma2(NEG1, q1, wv.y);
        unsigned long long vn = fma2(C2Q, v0, u1);
        p2 = s0; p1 = sn;
        q2 = v0; q1 = vn;
    }

    // --- store UNROTATED y = (s1 - cos*s2, sin*s2) per harmonic (no trig) ---
    {
        float x1A, x1B, x2A, x2B;
        upk(p1, x1A, x1B); upk(p2, x2A, x2B);
        sPart[seg * 64 + 4 * quad + 0] =
            make_float2(fmaf(-cthP.x, x2A, x1A), sthP.x * x2A);
        sPart[seg * 64 + 4 * quad + 1] =
            make_float2(fmaf(-cthP.y, x2B, x1B), sthP.y * x2B);
        upk(q1, x1A, x1B); upk(q2, x2A, x2B);
        sPart[seg * 64 + 4 * quad + 2] =
            make_float2(fmaf(-cthQ.x, x2A, x1A), sthQ.x * x2A);
        sPart[seg * 64 + 4 * quad + 3] =
            make_float2(fmaf(-cthQ.y, x2B, x1B), sthQ.y * x2B);
    }
    __syncthreads();   // barrier #2: partials visible

    // --- single-warp finish: lane l owns harmonics h = 2l, 2l+1.
    //     rot(s) = E63 * E64^s. Two independent phasor chains (even/odd s,
    //     step E128 = E64^2) halve the serial rotation dependency. ---
    if (tid < 32) {
        float4 e63 = *(const float4*)&sE63[2 * tid];  // (h0.re,h0.im,h1.re,h1.im)
        float4 e64 = *(const float4*)&sE64[2 * tid];
        // E128 = E64^2 per harmonic
        float e128_0re = fmaf(e64.x, e64.x, -e64.y * e64.y);
        float e128_0im = 2.0f * e64.x * e64.y;
        float e128_1re = fmaf(e64.z, e64.z, -e64.w * e64.w);
        float e128_1im = 2.0f * e64.z * e64.w;
        // even chain starts at E63, odd chain at E63*E64
        float ev0re = e63.x, ev0im = e63.y;
        float ev1re = e63.z, ev1im = e63.w;
        float od0re = fmaf(e63.x, e64.x, -e63.y * e64.y);
        float od0im = fmaf(e63.x, e64.y,  e63.y * e64.x);
        float od1re = fmaf(e63.z, e64.z, -e63.w * e64.w);
        float od1im = fmaf(e63.z, e64.w,  e63.w * e64.z);

        float ar0 = 0.0f, ai0 = 0.0f, ar1 = 0.0f, ai1 = 0.0f;
        #pragma unroll
        for (int s = 0; s < 16; s += 2) {
            float4 pq = *(const float4*)&sPart[s * 64 + 2 * tid];
            ar0 = fmaf(pq.x, ev0re, ar0); ar0 = fmaf(-pq.y, ev0im, ar0);
            ai0 = fmaf(pq.x, ev0im, ai0); ai0 = fmaf( pq.y, ev0re, ai0);
            ar1 = fmaf(pq.z, ev1re, ar1); ar1 = fmaf(-pq.w, ev1im, ar1);
            ai1 = fmaf(pq.z, ev1im, ai1); ai1 = fmaf( pq.w, ev1re, ai1);
            float4 pr = *(const float4*)&sPart[(s + 1) * 64 + 2 * tid];
            ar0 = fmaf(pr.x, od0re, ar0); ar0 = fmaf(-pr.y, od0im, ar0);
            ai0 = fmaf(pr.x, od0im, ai0); ai0 = fmaf( pr.y, od0re, ai0);
            ar1 = fmaf(pr.z, od1re, ar1); ar1 = fmaf(-pr.w, od1im, ar1);
            ai1 = fmaf(pr.z, od1im, ai1); ai1 = fmaf( pr.w, od1re, ai1);
            // advance both chains by E128 (independent)
            float t;
            t      = fmaf(ev0re, e128_0re, -ev0im * e128_0im);
            ev0im  = fmaf(ev0re, e128_0im,  ev0im * e128_0re); ev0re = t;
            t      = fmaf(ev1re, e128_1re, -ev1im * e128_1im);
            ev1im  = fmaf(ev1re, e128_1im,  ev1im * e128_1re); ev1re = t;
            t      = fmaf(od0re, e128_0re, -od0im * e128_0im);
            od0im  = fmaf(od0re, e128_0im,  od0im * e128_0re); od0re = t;
            t      = fmaf(od1re, e128_1re, -od1im * e128_1im);
            od1im  = fmaf(od1re, e128_1im,  od1im * e128_1re); od1re = t;
        }

        const float inv_sr2 = 1.0f / 16000.0f;
        float mag0 = sqrtf(ar0 * ar0 + ai0 * ai0);
        float mag1 = sqrtf(ar1 * ar1 + ai1 * ai1);
        float fch0 = f0v * (float)(2 * tid + 1) * inv_sr2;
        float fch1 = f0v * (float)(2 * tid + 2) * inv_sr2;
        if (fch0 > 0.5f) mag0 = 0.0f;   // Nyquist mask
        if (fch1 > 0.5f) mag1 = 0.0f;

        float s = mag0 + mag1;
        #pragma unroll
        for (int o = 16; o > 0; o >>= 1)
            s += __shfl_xor_sync(0xffffffffu, s, o);   // amp in all lanes

        float inv = 1.0f / s;
        ((float2*)out_hd)[f * 32 + tid] = make_float2(mag0 * inv, mag1 * inv);
        if (tid == 0)
            out_amp[f] = fminf(fmaxf(s * 2.0f, 0.0f), 1.0f);
    }
}

extern "C" void kernel_launch(void* const* d_in, const int* in_sizes, int n_in,
                              void* d_out, int out_size) {
    const float* audio = (const float*)d_in[0];
    const float* f0    = (const float*)d_in[1];
    const int frames   = in_sizes[1];  // 2*250*1 = 500
    float* out         = (float*)d_out;
    morlet_kernel<<<frames, 256>>>(audio, f0, out, out + (size_t)frames * 64);
}